// round 16
// baseline (speedup 1.0000x reference)
#include <cuda_runtime.h>
#include <cuda_bf16.h>
#include <cuda_fp16.h>
#include <math.h>
#include <stdint.h>

// Problem constants
#define BB   4
#define CC   128
#define NN   4096
#define HH   128
#define EPSV 1e-5f

typedef unsigned short ushort_t;

// ---------------- scratch (device globals; no allocations allowed) ----------
__device__ __align__(16) __half g_q16[BB * NN * HH];  // [b][n][h] fp16
__device__ __align__(16) __half g_k16[BB * NN * HH];  // [b][n][h] fp16
__device__ __align__(16) __half g_vth[BB * HH * NN];  // [b][h][n] fp16
__device__ __align__(16) float  g_o[BB * NN * HH];    // [b][n][h]
__device__ __align__(16) __half g_wq16[CC * HH];      // W fp16 [h][c]
__device__ __align__(16) __half g_wk16[CC * HH];
__device__ __align__(16) __half g_wv16[CC * HH];
__device__ float g_psum[128];
__device__ float g_psq[128];

// one dynamic-smem symbol, one type, for ALL kernels
extern __shared__ char dsm[];

// ======================= helpers (compute_103-safe only) ====================
__device__ __forceinline__ uint32_t smem_u32(const void* p) {
    uint32_t a;
    asm("{ .reg .u64 t; cvta.to.shared.u64 t, %1; cvt.u32.u64 %0, t; }"
        : "=r"(a) : "l"(p));
    return a;
}

#define CP_ASYNC16(dst, src) \
    asm volatile("cp.async.cg.shared.global [%0], [%1], 16;" \
                 :: "r"(dst), "l"(src))
#define CP_COMMIT() asm volatile("cp.async.commit_group;" ::: "memory")
#define CP_WAIT1()  asm volatile("cp.async.wait_group 1;" ::: "memory")
#define CP_WAIT0()  asm volatile("cp.async.wait_group 0;" ::: "memory")

__device__ __forceinline__ void ldsm4(uint32_t* r, uint32_t a) {
    asm volatile("ldmatrix.sync.aligned.m8n8.x4.shared.b16 {%0,%1,%2,%3}, [%4];"
                 : "=r"(r[0]), "=r"(r[1]), "=r"(r[2]), "=r"(r[3]) : "r"(a));
}

// fp16 mma, fp32 accum
__device__ __forceinline__ void mma16816f(float* c, const uint32_t* a, const uint32_t* b) {
    asm volatile("mma.sync.aligned.m16n8k16.row.col.f32.f16.f16.f32 "
                 "{%0,%1,%2,%3}, {%4,%5,%6,%7}, {%8,%9}, {%0,%1,%2,%3};"
                 : "+f"(c[0]), "+f"(c[1]), "+f"(c[2]), "+f"(c[3])
                 : "r"(a[0]), "r"(a[1]), "r"(a[2]), "r"(a[3]),
                   "r"(b[0]), "r"(b[1]));
}

__device__ __forceinline__ uint32_t sw128(uint32_t off) {
    return off ^ ((off >> 3) & 0x70);
}

// pack two fp32 into f16x2 (lo arg -> lower half)
__device__ __forceinline__ uint32_t pack_f16x2(float lo, float hi) {
    uint32_t d;
    asm("cvt.rn.f16x2.f32 %0, %1, %2;" : "=r"(d) : "f"(hi), "f"(lo));
    return d;
}

// ---------------------------------------------------------------------------
// Kernel 0: convert weights to fp16 + zero stats accumulators
// ---------------------------------------------------------------------------
__global__ void wsplit_kernel(const float* __restrict__ Wq,
                              const float* __restrict__ Wk,
                              const float* __restrict__ Wv)
{
    const int which = blockIdx.x, slice = blockIdx.y;
    if (which == 0 && slice == 0) {
        for (int e = threadIdx.x; e < 128; e += blockDim.x) {
            g_psum[e] = 0.0f;
            g_psq[e]  = 0.0f;
        }
    }
    const float* W = (which == 0) ? Wq : (which == 1) ? Wk : Wv;
    __half* dst = (which == 0) ? g_wq16 : (which == 1) ? g_wk16 : g_wv16;
    const int e = slice * 2048 + threadIdx.x * 4;
    *(uint2*)&dst[e] = make_uint2(pack_f16x2(W[e], W[e + 1]),
                                  pack_f16x2(W[e + 2], W[e + 3]));
}

// ---------------------------------------------------------------------------
// Kernel 1: QKV projection — single fp16 GEMM (proven R13).
// ---------------------------------------------------------------------------
#define QKV2_SMEM (68096 + 512)

__global__ __launch_bounds__(256, 1)
void qkv2_kernel(const float* __restrict__ x,
                 const float* __restrict__ bq, const float* __restrict__ bk,
                 const float* __restrict__ bv)
{
    const uint32_t sb = smem_u32(dsm);
    const int t = threadIdx.x, wid = t >> 5, lane = t & 31;
    const int n0 = blockIdx.x * 128, b = blockIdx.y, which = blockIdx.z;

    const __half* W16 = (which == 0) ? g_wq16 : (which == 1) ? g_wk16 : g_wv16;
    const float* bias = (which == 0) ? bq : (which == 1) ? bk : bv;

    float* bs = (float*)(dsm + 68096);
    if (t < 128) bs[t] = bias[t];

    #pragma unroll
    for (int e = t; e < 2048; e += 256) {
        int r = e >> 4, c8 = e & 15;
        uint32_t off = (uint32_t)((c8 >> 3) * 16384) +
                       sw128((uint32_t)(r * 128 + (c8 & 7) * 16));
        CP_ASYNC16(sb + 32768 + off, (const void*)(W16 + (size_t)r * CC + c8 * 8));
    }
    CP_COMMIT();

    const float* xp = x + (size_t)b * CC * NN + n0;
    #pragma unroll
    for (int e = t; e < 4096; e += 256) {
        int c = e >> 5, n4 = (e & 31) * 4;
        float4 v = *(const float4*)(xp + (size_t)c * NN + n4);
        uint32_t chunk = (c & 64) ? 16384u : 0u;
        int cc = (c & 63) * 2;
        float vv[4] = {v.x, v.y, v.z, v.w};
        #pragma unroll
        for (int i = 0; i < 4; ++i) {
            ushort_t h = __half_as_ushort(__float2half_rn(vv[i]));
            *(ushort_t*)(dsm + chunk + sw128((uint32_t)((n4 + i) * 128 + cc))) = h;
        }
    }
    CP_WAIT0();
    __syncthreads();

    const int R = (wid & 3) * 32, Cb = (wid >> 2) * 64;
    const int rA = lane & 15, kA = (lane >> 4) * 8;
    const int rB = ((lane >> 4) * 8) + (lane & 7), kB = ((lane >> 3) & 1) * 8;

    float acc[2][8][4];
    #pragma unroll
    for (int mf = 0; mf < 2; ++mf)
        #pragma unroll
        for (int nf = 0; nf < 8; ++nf)
            #pragma unroll
            for (int u = 0; u < 4; ++u) acc[mf][nf][u] = 0.0f;

    #pragma unroll
    for (int ks = 0; ks < 8; ++ks) {
        const uint32_t aB = sb + ((ks & 4) ? 16384u : 0u);
        const uint32_t bB = sb + 32768 + ((ks & 4) ? 16384u : 0u);
        const int kl = (ks & 3) * 16;
        uint32_t ah[2][4], bh[8][2];
        #pragma unroll
        for (int mf = 0; mf < 2; ++mf)
            ldsm4(ah[mf], aB + sw128((uint32_t)((R + mf * 16 + rA) * 128 + (kl + kA) * 2)));
        #pragma unroll
        for (int np = 0; np < 4; ++np) {
            uint32_t r4[4];
            ldsm4(r4, bB + sw128((uint32_t)((Cb + np * 16 + rB) * 128 + (kl + kB) * 2)));
            bh[2 * np][0] = r4[0]; bh[2 * np][1] = r4[1];
            bh[2 * np + 1][0] = r4[2]; bh[2 * np + 1][1] = r4[3];
        }
        #pragma unroll
        for (int mf = 0; mf < 2; ++mf)
            #pragma unroll
            for (int nf = 0; nf < 8; ++nf)
                mma16816f(acc[mf][nf], ah[mf], bh[nf]);
    }
    __syncthreads();

    float* sf = (float*)dsm;
    const int rowl = lane >> 2, coll = (lane & 3) * 2;
    #pragma unroll
    for (int mf = 0; mf < 2; ++mf)
        #pragma unroll
        for (int nf = 0; nf < 8; ++nf) {
            int col = Cb + nf * 8 + coll;
            float b0 = bs[col], b1 = bs[col + 1];
            float* p = sf + (size_t)(R + mf * 16 + rowl) * 133 + col;
            p[0] = acc[mf][nf][0] + b0;
            p[1] = acc[mf][nf][1] + b1;
            p[8 * 133 + 0] = acc[mf][nf][2] + b0;
            p[8 * 133 + 1] = acc[mf][nf][3] + b1;
        }
    __syncthreads();

    if (which < 2) {
        __half* dst16 = which ? g_k16 : g_q16;
        #pragma unroll
        for (int e = t; e < 4096; e += 256) {
            int r = e >> 5, c4 = (e & 31) * 4;
            float* p = sf + (size_t)r * 133 + c4;
            size_t idx = ((size_t)(b * NN + n0 + r)) * HH + c4;
            *(uint2*)&dst16[idx] = make_uint2(pack_f16x2(p[0], p[1]),
                                              pack_f16x2(p[2], p[3]));
        }
    } else {
        #pragma unroll
        for (int e = t; e < 4096; e += 256) {
            int h = e >> 5, n4 = (e & 31) * 4;
            float f0 = sf[(size_t)(n4 + 0) * 133 + h];
            float f1 = sf[(size_t)(n4 + 1) * 133 + h];
            float f2 = sf[(size_t)(n4 + 2) * 133 + h];
            float f3 = sf[(size_t)(n4 + 3) * 133 + h];
            size_t idx = (size_t)b * HH * NN + (size_t)h * NN + n0 + n4;
            *(uint2*)&g_vth[idx] = make_uint2(pack_f16x2(f0, f1), pack_f16x2(f2, f3));
        }
    }
}

// ===========================================================================
// Kernel 2: fused flash attention v10 — BI=64, 8 warps (4m x 2 j-halves),
// per-warp softmax maxima (merged once at epilogue), 2 CTAs/SM ->
// 4 warps/SMSP to hide the max/exp chain under other warps' MMA streams.
// smem: Q [64][128]f16 2 chunks @0/8K (16K); stage s @16K + s*32K (2 stages):
//   K [64][128] 2 chunks @+0/+8K, V [128][64] @+16K.
// epilogue: sf0 @0 (33792), sf1 @33792, mrow @67584, lrow @68096,
//           red @68608 (4K), red2 @72704 (4K).
// ===========================================================================
#define FL_SMEM  81920
#define FL_NIT   64

__device__ __forceinline__ void fl_load(uint32_t stg, int b, int j0, int t)
{
    const __half* kp = g_k16 + ((size_t)(b * NN + j0)) * HH;
    #pragma unroll
    for (int e = t; e < 1024; e += 256) {           // 64 rows x 16 cp16
        int r = e >> 4, c8 = e & 15;
        uint32_t off = (uint32_t)((c8 >> 3) * 8192) +
                       sw128((uint32_t)(r * 128 + (c8 & 7) * 16));
        CP_ASYNC16(stg + off, (const void*)(kp + (size_t)r * HH + c8 * 8));
    }
    const __half* vh = g_vth + (size_t)b * HH * NN + j0;
    #pragma unroll
    for (int e = t; e < 1024; e += 256) {           // 128 rows x 8 cp16
        int r = e >> 3, c = e & 7;
        uint32_t off = sw128((uint32_t)(r * 128 + c * 16));
        CP_ASYNC16(stg + 16384 + off, (const void*)(vh + (size_t)r * NN + c * 8));
    }
    CP_COMMIT();
}

__global__ __launch_bounds__(256, 2)
void flash_kernel()
{
    const uint32_t sb = smem_u32(dsm);
    const int t = threadIdx.x, wid = t >> 5, lane = t & 31;
    const int i0 = blockIdx.x * 64, b = blockIdx.y;
    const int m  = wid & 3, nh = wid >> 2;   // 4 m-slots x 2 j-halves
    const int R  = m * 16;                   // warp's 16 rows
    const int Jw = nh * 32;                  // warp's j-half within the 64-tile

    // Q tile load (group 0): [64][128] fp16, 2 column-chunks of 8KB
    {
        const __half* qp = g_q16 + ((size_t)(b * NN + i0)) * HH;
        #pragma unroll
        for (int e = t; e < 1024; e += 256) {
            int r = e >> 4, c8 = e & 15;
            uint32_t off = (uint32_t)((c8 >> 3) * 8192) +
                           sw128((uint32_t)(r * 128 + (c8 & 7) * 16));
            CP_ASYNC16(sb + off, (const void*)(qp + (size_t)r * HH + c8 * 8));
        }
        CP_COMMIT();
    }
    fl_load(sb + 16384, b, 0,  t);          // group 1 (stage 0)
    fl_load(sb + 49152, b, 64, t);          // group 2 (stage 1)

    const int rA = lane & 15, kA = (lane >> 4) * 8;
    const int rB = ((lane >> 4) * 8) + (lane & 7), kB = ((lane >> 3) & 1) * 8;

    float oacc[16][4];
    #pragma unroll
    for (int nf = 0; nf < 16; ++nf)
        #pragma unroll
        for (int u = 0; u < 4; ++u) oacc[nf][u] = 0.0f;
    float lsum0 = 0.0f, lsum1 = 0.0f;
    float m0 = -1e30f, m1 = -1e30f;

    for (int c = 0; c < FL_NIT; ++c) {
        if (c < FL_NIT - 1) CP_WAIT1(); else CP_WAIT0();
        __syncthreads();
        const uint32_t stg = sb + 16384 + (uint32_t)(c & 1) * 32768;

        // ---------- S = Q K^T : warp's 16 rows x its 32-j half ----------
        float sacc[4][4];
        #pragma unroll
        for (int nf = 0; nf < 4; ++nf)
            #pragma unroll
            for (int u = 0; u < 4; ++u) sacc[nf][u] = 0.0f;

        #pragma unroll
        for (int ks = 0; ks < 8; ++ks) {
            const uint32_t qb = sb  + ((ks & 4) ? 8192u : 0u);
            const uint32_t kb = stg + ((ks & 4) ? 8192u : 0u);
            const int kl = (ks & 3) * 16;
            uint32_t ah[4];
            ldsm4(ah, qb + sw128((uint32_t)((R + rA) * 128 + (kl + kA) * 2)));
            #pragma unroll
            for (int np = 0; np < 2; ++np) {
                uint32_t r4[4];
                ldsm4(r4, kb + sw128((uint32_t)((Jw + np * 16 + rB) * 128 + (kl + kB) * 2)));
                uint32_t b0[2] = {r4[0], r4[1]}, b1[2] = {r4[2], r4[3]};
                mma16816f(sacc[2 * np],     ah, b0);
                mma16816f(sacc[2 * np + 1], ah, b1);
            }
        }

        // ---------- per-warp online max (valid upper bound on own j) ----------
        float m0t = -1e30f, m1t = -1e30f;
        #pragma unroll
        for (int nf = 0; nf < 4; ++nf) {
            m0t = fmaxf(m0t, fmaxf(sacc[nf][0], sacc[nf][1]));
            m1t = fmaxf(m1t, fmaxf(sacc[nf][2], sacc[nf][3]));
        }
        m0t = fmaxf(m0t, __shfl_xor_sync(~0u, m0t, 1));
        m0t = fmaxf(m0t, __shfl_xor_sync(~0u, m0t, 2));
        m1t = fmaxf(m1t, __shfl_xor_sync(~0u, m1t, 1));
        m1t = fmaxf(m1t, __shfl_xor_sync(~0u, m1t, 2));
        float m0n = fmaxf(m0, m0t), m1n = fmaxf(m1, m1t);
        float sc0 = __expf(m0 - m0n), sc1 = __expf(m1 - m1n);
        m0 = m0n; m1 = m1n;
        if (sc0 < 1.0f || sc1 < 1.0f) {
            lsum0 *= sc0; lsum1 *= sc1;
            #pragma unroll
            for (int nf = 0; nf < 16; ++nf) {
                oacc[nf][0] *= sc0; oacc[nf][1] *= sc0;
                oacc[nf][2] *= sc1; oacc[nf][3] *= sc1;
            }
        }

        // ---------- exp(s - m) -> fp16 P fragments (2 k-steps) ----------
        uint32_t ph[2][4];
        float rs0 = 0.0f, rs1 = 0.0f;
        #pragma unroll
        for (int nf = 0; nf < 4; ++nf) {
            float e0 = __expf(sacc[nf][0] - m0);
            float e1 = __expf(sacc[nf][1] - m0);
            float e2 = __expf(sacc[nf][2] - m1);
            float e3 = __expf(sacc[nf][3] - m1);
            rs0 += e0 + e1;
            rs1 += e2 + e3;
            const int ks = nf >> 1, o = (nf & 1) * 2;
            ph[ks][o]     = pack_f16x2(e0, e1);
            ph[ks][o + 1] = pack_f16x2(e2, e3);
        }
        lsum0 += rs0;
        lsum1 += rs1;

        // ---------- O += P V over the warp's k-half (j in [Jw, Jw+32)) -------
        #pragma unroll
        for (int ks = 0; ks < 2; ++ks) {
            #pragma unroll
            for (int np = 0; np < 8; ++np) {
                uint32_t r4[4];
                ldsm4(r4, stg + 16384 +
                          sw128((uint32_t)((np * 16 + rB) * 128 + (Jw + ks * 16 + kB) * 2)));
                uint32_t b0[2] = {r4[0], r4[1]}, b1[2] = {r4[2], r4[3]};
                mma16816f(oacc[2 * np],     ph[ks], b0);
                mma16816f(oacc[2 * np + 1], ph[ks], b1);
            }
        }
        __syncthreads();    // stage fully consumed before reload overwrites it

        if (c + 2 < FL_NIT)
            fl_load(sb + 16384 + (uint32_t)(c & 1) * 32768, b, (c + 2) * 64, t);
    }

    // ---------------- epilogue: merge the two j-halves per row ---------------
    // quad-reduce l partials (m is already quad-uniform)
    lsum0 += __shfl_xor_sync(~0u, lsum0, 1);
    lsum0 += __shfl_xor_sync(~0u, lsum0, 2);
    lsum1 += __shfl_xor_sync(~0u, lsum1, 1);
    lsum1 += __shfl_xor_sync(~0u, lsum1, 2);

    float* mrow = (float*)(dsm + 67584);    // [64 rows][2 halves]
    float* lrow = (float*)(dsm + 68096);    // [64 rows][2 halves]
    const int rowl = lane >> 2, coll = (lane & 3) * 2;
    __syncthreads();                         // main-loop smem reads done
    if ((lane & 3) == 0) {
        mrow[(R + rowl) * 2 + nh]     = m0;
        lrow[(R + rowl) * 2 + nh]     = lsum0;
        mrow[(R + 8 + rowl) * 2 + nh] = m1;
        lrow[(R + 8 + rowl) * 2 + nh] = lsum1;
    }
    __syncthreads();
    // own-scale factors: f = e^{m_own-M} / (l_own e^{m_own-M} + l_other e^{m_oth-M})
    float f0, f1;
    {
        float mB = mrow[(R + rowl) * 2 + (1 - nh)];
        float lB = lrow[(R + rowl) * 2 + (1 - nh)];
        float M = fmaxf(m0, mB);
        float sA = __expf(m0 - M), sB2 = __expf(mB - M);
        f0 = sA / (lsum0 * sA + lB * sB2);
        mB = mrow[(R + 8 + rowl) * 2 + (1 - nh)];
        lB = lrow[(R + 8 + rowl) * 2 + (1 - nh)];
        M = fmaxf(m1, mB);
        sA = __expf(m1 - M); sB2 = __expf(mB - M);
        f1 = sA / (lsum1 * sA + lB * sB2);
    }
    // write scaled halves to separate staging areas
    float* sfh = (float*)(dsm + (size_t)nh * 33792);   // [64][132]
    #pragma unroll
    for (int nf = 0; nf < 16; ++nf) {
        float* p0 = sfh + (size_t)(R + rowl) * 132 + nf * 8 + coll;
        float* p1 = sfh + (size_t)(R + 8 + rowl) * 132 + nf * 8 + coll;
        p0[0] = oacc[nf][0] * f0;
        p0[1] = oacc[nf][1] * f0;
        p1[0] = oacc[nf][2] * f1;
        p1[1] = oacc[nf][3] * f1;
    }
    __syncthreads();

    // combine halves, store, fused BN partial stats
    float* sf0 = (float*)dsm;
    float* sf1 = (float*)(dsm + 33792);
    float* dst = g_o + ((size_t)(b * NN + i0)) * HH;
    float s4a[4] = {0.f, 0.f, 0.f, 0.f}, q4[4] = {0.f, 0.f, 0.f, 0.f};
    #pragma unroll
    for (int e = t; e < 2048; e += 256) {    // 64 rows x 32 float4-cols
        int r = e >> 5, c4 = (e & 31) * 4;
        float4 a = *(float4*)(sf0 + (size_t)r * 132 + c4);
        float4 bv2 = *(float4*)(sf1 + (size_t)r * 132 + c4);
        float4 v = make_float4(a.x + bv2.x, a.y + bv2.y, a.z + bv2.z, a.w + bv2.w);
        *(float4*)(dst + (size_t)r * HH + c4) = v;
        s4a[0] += v.x; q4[0] += v.x * v.x;
        s4a[1] += v.y; q4[1] += v.y * v.y;
        s4a[2] += v.z; q4[2] += v.z * v.z;
        s4a[3] += v.w; q4[3] += v.w * v.w;
    }
    float* red  = (float*)(dsm + 68608);     // [128 ch][8 grp]
    float* red2 = (float*)(dsm + 72704);     // [128 ch][8 grp]
    const int cbase = (t & 31) * 4, grp = t >> 5;
    #pragma unroll
    for (int i = 0; i < 4; ++i) {
        red[(cbase + i) * 8 + grp]  = s4a[i];
        red2[(cbase + i) * 8 + grp] = q4[i];
    }
    __syncthreads();
    if (t < 128) {
        float ss = 0.0f, qq = 0.0f;
        #pragma unroll
        for (int g2 = 0; g2 < 8; ++g2) {
            ss += red[t * 8 + g2];
            qq += red2[t * 8 + g2];
        }
        atomicAdd(&g_psum[t], ss);
        atomicAdd(&g_psq[t], qq);
    }
}

// ---------------------------------------------------------------------------
// Kernel 3: fused BN epilogue (stats finalize inlined; smem tile transpose)
// ---------------------------------------------------------------------------
__global__ __launch_bounds__(256, 1)
void final_kernel(const float* __restrict__ x,
                  const float* __restrict__ bnw,
                  const float* __restrict__ bnb,
                  const float* __restrict__ gamma,
                  float* __restrict__ out)
{
    __shared__ float sO[32 * 132];
    const int b = blockIdx.y, n0 = blockIdx.x * 32;
    const int t = threadIdx.x;

    #pragma unroll
    for (int e = t; e < 1024; e += 256) {
        int r = e >> 5, c4 = (e & 31) * 4;
        *(float4*)&sO[r * 132 + c4] =
            *(const float4*)&g_o[((size_t)(b * NN + n0 + r)) * HH + c4];
    }
    __syncthreads();
    const float g = __ldg(gamma);
    const float invn = 1.0f / 16384.0f;
    #pragma unroll
    for (int e = t; e < 1024; e += 256) {
        int c = e >> 3, n4 = (e & 7) * 4;
        float mean = g_psum[c] * invn;
        float var = g_psq[c] * invn - mean * mean;
        float rstd = rsqrtf(var + EPSV);
        float wc = __ldg(&bnw[c]), bc = __ldg(&bnb[c]);
        size_t gi = ((size_t)(b * CC + c)) * NN + n0 + n4;
        float4 xv = *(const float4*)&x[gi];
        float4 r;
        r.x = g * ((sO[(n4 + 0) * 132 + c] - mean) * rstd * wc + bc) + xv.x;
        r.y = g * ((sO[(n4 + 1) * 132 + c] - mean) * rstd * wc + bc) + xv.y;
        r.z = g * ((sO[(n4 + 2) * 132 + c] - mean) * rstd * wc + bc) + xv.z;
        r.w = g * ((sO[(n4 + 3) * 132 + c] - mean) * rstd * wc + bc) + xv.w;
        *(float4*)&out[gi] = r;
    }
}

// ---------------------------------------------------------------------------
extern "C" void kernel_launch(void* const* d_in, const int* in_sizes, int n_in,
                              void* d_out, int out_size)
{
    (void)in_sizes; (void)n_in; (void)out_size;
    const float* x     = (const float*)d_in[0];
    const float* Wq    = (const float*)d_in[1];
    const float* bq    = (const float*)d_in[2];
    const float* Wk    = (const float*)d_in[3];
    const float* bk    = (const float*)d_in[4];
    const float* Wv    = (const float*)d_in[5];
    const float* bv    = (const float*)d_in[6];
    const float* bnw   = (const float*)d_in[7];
    const float* bnb   = (const float*)d_in[8];
    const float* gamma = (const float*)d_in[9];
    float* out = (float*)d_out;

    cudaFuncSetAttribute(qkv2_kernel,  cudaFuncAttributeMaxDynamicSharedMemorySize, QKV2_SMEM);
    cudaFuncSetAttribute(flash_kernel, cudaFuncAttributeMaxDynamicSharedMemorySize, FL_SMEM);

    wsplit_kernel<<<dim3(3, 8), 512>>>(Wq, Wk, Wv);
    qkv2_kernel<<<dim3(NN / 128, BB, 3), 256, QKV2_SMEM>>>(x, bq, bk, bv);
    flash_kernel<<<dim3(NN / 64, BB), 256, FL_SMEM>>>();
    final_kernel<<<dim3(NN / 32, BB), 256>>>(x, bnw, bnb, gamma, out);
}

// round 17
// speedup vs baseline: 1.2161x; 1.2161x over previous
#include <cuda_runtime.h>
#include <cuda_bf16.h>
#include <cuda_fp16.h>
#include <math.h>
#include <stdint.h>

// Problem constants
#define BB   4
#define CC   128
#define NN   4096
#define HH   128
#define EPSV 1e-5f

typedef unsigned short ushort_t;

// ---------------- scratch (device globals; no allocations allowed) ----------
__device__ __align__(16) __half g_q16[BB * NN * HH];  // [b][n][h] fp16
__device__ __align__(16) __half g_k16[BB * NN * HH];  // [b][n][h] fp16
__device__ __align__(16) __half g_vth[BB * HH * NN];  // [b][h][n] fp16
__device__ __align__(16) float  g_o[BB * NN * HH];    // [b][n][h]
__device__ float g_psum[128];
__device__ float g_psq[128];

// one dynamic-smem symbol, one type, for ALL kernels
extern __shared__ char dsm[];

// ======================= helpers (compute_103-safe only) ====================
__device__ __forceinline__ uint32_t smem_u32(const void* p) {
    uint32_t a;
    asm("{ .reg .u64 t; cvta.to.shared.u64 t, %1; cvt.u32.u64 %0, t; }"
        : "=r"(a) : "l"(p));
    return a;
}

#define CP_ASYNC16(dst, src) \
    asm volatile("cp.async.cg.shared.global [%0], [%1], 16;" \
                 :: "r"(dst), "l"(src))
#define CP_COMMIT() asm volatile("cp.async.commit_group;" ::: "memory")
#define CP_WAIT2()  asm volatile("cp.async.wait_group 2;" ::: "memory")
#define CP_WAIT1()  asm volatile("cp.async.wait_group 1;" ::: "memory")
#define CP_WAIT0()  asm volatile("cp.async.wait_group 0;" ::: "memory")

__device__ __forceinline__ void ldsm4(uint32_t* r, uint32_t a) {
    asm volatile("ldmatrix.sync.aligned.m8n8.x4.shared.b16 {%0,%1,%2,%3}, [%4];"
                 : "=r"(r[0]), "=r"(r[1]), "=r"(r[2]), "=r"(r[3]) : "r"(a));
}

// fp16 mma, fp32 accum
__device__ __forceinline__ void mma16816f(float* c, const uint32_t* a, const uint32_t* b) {
    asm volatile("mma.sync.aligned.m16n8k16.row.col.f32.f16.f16.f32 "
                 "{%0,%1,%2,%3}, {%4,%5,%6,%7}, {%8,%9}, {%0,%1,%2,%3};"
                 : "+f"(c[0]), "+f"(c[1]), "+f"(c[2]), "+f"(c[3])
                 : "r"(a[0]), "r"(a[1]), "r"(a[2]), "r"(a[3]),
                   "r"(b[0]), "r"(b[1]));
}

__device__ __forceinline__ uint32_t sw128(uint32_t off) {
    return off ^ ((off >> 3) & 0x70);
}

// pack two fp32 into f16x2 (lo arg -> lower half)
__device__ __forceinline__ uint32_t pack_f16x2(float lo, float hi) {
    uint32_t d;
    asm("cvt.rn.f16x2.f32 %0, %1, %2;" : "=r"(d) : "f"(hi), "f"(lo));
    return d;
}

// ---------------------------------------------------------------------------
// Kernel 1: QKV projection — single fp16 GEMM; W loaded fp32 + converted
// inline (wsplit kernel eliminated).  grid (32 n-tiles, 4 b, 3 which), 256 thr.
// smem: As [128n][128c]f16 2 chunks @0/16K (32K); Bs (W) @32K 2 chunks (32K);
//       fp32 staging [128][133] reuses @0; bias @68096.
// ---------------------------------------------------------------------------
#define QKV2_SMEM (68096 + 512)

__global__ __launch_bounds__(256, 1)
void qkv2_kernel(const float* __restrict__ x,
                 const float* __restrict__ Wq, const float* __restrict__ Wk,
                 const float* __restrict__ Wv,
                 const float* __restrict__ bq, const float* __restrict__ bk,
                 const float* __restrict__ bv)
{
    const uint32_t sb = smem_u32(dsm);
    const int t = threadIdx.x, wid = t >> 5, lane = t & 31;
    const int n0 = blockIdx.x * 128, b = blockIdx.y, which = blockIdx.z;

    // zero BN stat accumulators once (qkv2 completes before flash launches)
    if (n0 == 0 && b == 0 && which == 0 && t < 128) {
        g_psum[t] = 0.0f;
        g_psq[t]  = 0.0f;
    }

    const float* W    = (which == 0) ? Wq : (which == 1) ? Wk : Wv;
    const float* bias = (which == 0) ? bq : (which == 1) ? bk : bv;

    float* bs = (float*)(dsm + 68096);
    if (t < 128) bs[t] = bias[t];

    // W fp32 -> fp16 smem Bs [128h][128c], 2 column-chunks, inline convert
    #pragma unroll
    for (int e = t; e < 2048; e += 256) {
        int r = e >> 4, c8 = e & 15;
        const float* wp = W + (size_t)r * CC + c8 * 8;
        float4 w0 = *(const float4*)(wp);
        float4 w1 = *(const float4*)(wp + 4);
        uint4 pk = make_uint4(pack_f16x2(w0.x, w0.y), pack_f16x2(w0.z, w0.w),
                              pack_f16x2(w1.x, w1.y), pack_f16x2(w1.z, w1.w));
        uint32_t off = (uint32_t)((c8 >> 3) * 16384) +
                       sw128((uint32_t)(r * 128 + (c8 & 7) * 16));
        *(uint4*)(dsm + 32768 + off) = pk;
    }

    // x tile [128c][128n] fp32 -> fp16, transposed into As [128n][128c]
    const float* xp = x + (size_t)b * CC * NN + n0;
    #pragma unroll
    for (int e = t; e < 4096; e += 256) {
        int c = e >> 5, n4 = (e & 31) * 4;
        float4 v = *(const float4*)(xp + (size_t)c * NN + n4);
        uint32_t chunk = (c & 64) ? 16384u : 0u;
        int cc = (c & 63) * 2;
        float vv[4] = {v.x, v.y, v.z, v.w};
        #pragma unroll
        for (int i = 0; i < 4; ++i) {
            ushort_t h = __half_as_ushort(__float2half_rn(vv[i]));
            *(ushort_t*)(dsm + chunk + sw128((uint32_t)((n4 + i) * 128 + cc))) = h;
        }
    }
    __syncthreads();

    // GEMM D[128n][128h], warps 4m x 2n, single fp16 term
    const int R = (wid & 3) * 32, Cb = (wid >> 2) * 64;
    const int rA = lane & 15, kA = (lane >> 4) * 8;
    const int rB = ((lane >> 4) * 8) + (lane & 7), kB = ((lane >> 3) & 1) * 8;

    float acc[2][8][4];
    #pragma unroll
    for (int mf = 0; mf < 2; ++mf)
        #pragma unroll
        for (int nf = 0; nf < 8; ++nf)
            #pragma unroll
            for (int u = 0; u < 4; ++u) acc[mf][nf][u] = 0.0f;

    #pragma unroll
    for (int ks = 0; ks < 8; ++ks) {
        const uint32_t aB = sb + ((ks & 4) ? 16384u : 0u);
        const uint32_t bB = sb + 32768 + ((ks & 4) ? 16384u : 0u);
        const int kl = (ks & 3) * 16;
        uint32_t ah[2][4], bh[8][2];
        #pragma unroll
        for (int mf = 0; mf < 2; ++mf)
            ldsm4(ah[mf], aB + sw128((uint32_t)((R + mf * 16 + rA) * 128 + (kl + kA) * 2)));
        #pragma unroll
        for (int np = 0; np < 4; ++np) {
            uint32_t r4[4];
            ldsm4(r4, bB + sw128((uint32_t)((Cb + np * 16 + rB) * 128 + (kl + kB) * 2)));
            bh[2 * np][0] = r4[0]; bh[2 * np][1] = r4[1];
            bh[2 * np + 1][0] = r4[2]; bh[2 * np + 1][1] = r4[3];
        }
        #pragma unroll
        for (int mf = 0; mf < 2; ++mf)
            #pragma unroll
            for (int nf = 0; nf < 8; ++nf)
                mma16816f(acc[mf][nf], ah[mf], bh[nf]);
    }
    __syncthreads();

    float* sf = (float*)dsm;
    const int rowl = lane >> 2, coll = (lane & 3) * 2;
    #pragma unroll
    for (int mf = 0; mf < 2; ++mf)
        #pragma unroll
        for (int nf = 0; nf < 8; ++nf) {
            int col = Cb + nf * 8 + coll;
            float b0 = bs[col], b1 = bs[col + 1];
            float* p = sf + (size_t)(R + mf * 16 + rowl) * 133 + col;
            p[0] = acc[mf][nf][0] + b0;
            p[1] = acc[mf][nf][1] + b1;
            p[8 * 133 + 0] = acc[mf][nf][2] + b0;
            p[8 * 133 + 1] = acc[mf][nf][3] + b1;
        }
    __syncthreads();

    if (which < 2) {
        __half* dst16 = which ? g_k16 : g_q16;
        #pragma unroll
        for (int e = t; e < 4096; e += 256) {
            int r = e >> 5, c4 = (e & 31) * 4;
            float* p = sf + (size_t)r * 133 + c4;
            size_t idx = ((size_t)(b * NN + n0 + r)) * HH + c4;
            *(uint2*)&dst16[idx] = make_uint2(pack_f16x2(p[0], p[1]),
                                              pack_f16x2(p[2], p[3]));
        }
    } else {
        // V: write transposed fp16 Vt [b][h][n]
        #pragma unroll
        for (int e = t; e < 4096; e += 256) {
            int h = e >> 5, n4 = (e & 31) * 4;
            float f0 = sf[(size_t)(n4 + 0) * 133 + h];
            float f1 = sf[(size_t)(n4 + 1) * 133 + h];
            float f2 = sf[(size_t)(n4 + 2) * 133 + h];
            float f3 = sf[(size_t)(n4 + 3) * 133 + h];
            size_t idx = (size_t)b * HH * NN + (size_t)h * NN + n0 + n4;
            *(uint2*)&g_vth[idx] = make_uint2(pack_f16x2(f0, f1), pack_f16x2(f2, f3));
        }
    }
}

// ===========================================================================
// Kernel 2: fused flash attention (R15-proven) — BI=64, 4 warps, 2 CTAs/SM,
// Q fragments hoisted into registers.
// smem: Q [64][128]f16 2 chunks @0/8K (16K); stage s @16K + s*32K (2 stages).
// ===========================================================================
#define FL_SMEM  81920
#define FL_NIT   64

__device__ __forceinline__ void fl_load(uint32_t stg, int b, int j0, int t)
{
    const __half* kp = g_k16 + ((size_t)(b * NN + j0)) * HH;
    #pragma unroll
    for (int e = t; e < 1024; e += 128) {           // 64 rows x 16 cp16
        int r = e >> 4, c8 = e & 15;
        uint32_t off = (uint32_t)((c8 >> 3) * 8192) +
                       sw128((uint32_t)(r * 128 + (c8 & 7) * 16));
        CP_ASYNC16(stg + off, (const void*)(kp + (size_t)r * HH + c8 * 8));
    }
    const __half* vh = g_vth + (size_t)b * HH * NN + j0;
    #pragma unroll
    for (int e = t; e < 1024; e += 128) {           // 128 rows x 8 cp16
        int r = e >> 3, c = e & 7;
        uint32_t off = sw128((uint32_t)(r * 128 + c * 16));
        CP_ASYNC16(stg + 16384 + off, (const void*)(vh + (size_t)r * NN + c * 8));
    }
    CP_COMMIT();
}

__global__ __launch_bounds__(128, 2)
void flash_kernel()
{
    const uint32_t sb = smem_u32(dsm);
    const int t = threadIdx.x, wid = t >> 5, lane = t & 31;
    const int i0 = blockIdx.x * 64, b = blockIdx.y;
    const int R = wid * 16;                 // 4 warps x 16 rows = 64 rows

    // Q tile load (group 0)
    {
        const __half* qp = g_q16 + ((size_t)(b * NN + i0)) * HH;
        #pragma unroll
        for (int e = t; e < 1024; e += 128) {
            int r = e >> 4, c8 = e & 15;
            uint32_t off = (uint32_t)((c8 >> 3) * 8192) +
                           sw128((uint32_t)(r * 128 + (c8 & 7) * 16));
            CP_ASYNC16(sb + off, (const void*)(qp + (size_t)r * HH + c8 * 8));
        }
        CP_COMMIT();
    }
    fl_load(sb + 16384, b, 0,  t);          // group 1 (stage 0)
    fl_load(sb + 49152, b, 64, t);          // group 2 (stage 1)

    const int rA = lane & 15, kA = (lane >> 4) * 8;
    const int rB = ((lane >> 4) * 8) + (lane & 7), kB = ((lane >> 3) & 1) * 8;

    // ---- hoist Q fragments into registers (loop-invariant) ----
    CP_WAIT2();                              // group 0 (Q) complete
    __syncthreads();
    uint32_t qfrag[8][4];
    #pragma unroll
    for (int ks = 0; ks < 8; ++ks) {
        const uint32_t qb = sb + ((ks & 4) ? 8192u : 0u);
        const int kl = (ks & 3) * 16;
        ldsm4(qfrag[ks], qb + sw128((uint32_t)((R + rA) * 128 + (kl + kA) * 2)));
    }

    float oacc[16][4];
    #pragma unroll
    for (int nf = 0; nf < 16; ++nf)
        #pragma unroll
        for (int u = 0; u < 4; ++u) oacc[nf][u] = 0.0f;
    float lsum0 = 0.0f, lsum1 = 0.0f;
    float m0 = -1e30f, m1 = -1e30f;

    for (int c = 0; c < FL_NIT; ++c) {
        if (c < FL_NIT - 1) CP_WAIT1(); else CP_WAIT0();
        __syncthreads();
        const uint32_t stg = sb + 16384 + (uint32_t)(c & 1) * 32768;

        // ---------- S = Q K^T : fp16, A resident in registers ----------
        float sacc[8][4];
        #pragma unroll
        for (int nf = 0; nf < 8; ++nf)
            #pragma unroll
            for (int u = 0; u < 4; ++u) sacc[nf][u] = 0.0f;

        #pragma unroll
        for (int ks = 0; ks < 8; ++ks) {
            const uint32_t kb = stg + ((ks & 4) ? 8192u : 0u);
            const int kl = (ks & 3) * 16;
            #pragma unroll
            for (int np = 0; np < 4; ++np) {
                uint32_t r4[4];
                ldsm4(r4, kb + sw128((uint32_t)((np * 16 + rB) * 128 + (kl + kB) * 2)));
                uint32_t b0[2] = {r4[0], r4[1]}, b1[2] = {r4[2], r4[3]};
                mma16816f(sacc[2 * np],     qfrag[ks], b0);
                mma16816f(sacc[2 * np + 1], qfrag[ks], b1);
            }
        }

        // ---------- online max update (+rescale only when max moved) ----------
        float m0t = -1e30f, m1t = -1e30f;
        #pragma unroll
        for (int nf = 0; nf < 8; ++nf) {
            m0t = fmaxf(m0t, fmaxf(sacc[nf][0], sacc[nf][1]));
            m1t = fmaxf(m1t, fmaxf(sacc[nf][2], sacc[nf][3]));
        }
        m0t = fmaxf(m0t, __shfl_xor_sync(~0u, m0t, 1));
        m0t = fmaxf(m0t, __shfl_xor_sync(~0u, m0t, 2));
        m1t = fmaxf(m1t, __shfl_xor_sync(~0u, m1t, 1));
        m1t = fmaxf(m1t, __shfl_xor_sync(~0u, m1t, 2));
        float m0n = fmaxf(m0, m0t), m1n = fmaxf(m1, m1t);
        float sc0 = __expf(m0 - m0n), sc1 = __expf(m1 - m1n);
        m0 = m0n; m1 = m1n;
        if (sc0 < 1.0f || sc1 < 1.0f) {     // exact: expf(0)==1
            lsum0 *= sc0; lsum1 *= sc1;
            #pragma unroll
            for (int nf = 0; nf < 16; ++nf) {
                oacc[nf][0] *= sc0; oacc[nf][1] *= sc0;
                oacc[nf][2] *= sc1; oacc[nf][3] *= sc1;
            }
        }

        // ---------- exp(s - m) -> fp16 P fragments ----------
        uint32_t ph[4][4];
        float rs0 = 0.0f, rs1 = 0.0f;
        #pragma unroll
        for (int nf = 0; nf < 8; ++nf) {
            float e0 = __expf(sacc[nf][0] - m0);
            float e1 = __expf(sacc[nf][1] - m0);
            float e2 = __expf(sacc[nf][2] - m1);
            float e3 = __expf(sacc[nf][3] - m1);
            rs0 += e0 + e1;
            rs1 += e2 + e3;
            const int ks = nf >> 1, o = (nf & 1) * 2;
            ph[ks][o]     = pack_f16x2(e0, e1);
            ph[ks][o + 1] = pack_f16x2(e2, e3);
        }
        lsum0 += rs0;
        lsum1 += rs1;

        // ---------- O += P V : fp16, single V ----------
        #pragma unroll
        for (int ks = 0; ks < 4; ++ks) {
            #pragma unroll
            for (int np = 0; np < 8; ++np) {
                uint32_t r4[4];
                ldsm4(r4, stg + 16384 +
                          sw128((uint32_t)((np * 16 + rB) * 128 + (ks * 16 + kB) * 2)));
                uint32_t b0[2] = {r4[0], r4[1]}, b1[2] = {r4[2], r4[3]};
                mma16816f(oacc[2 * np],     ph[ks], b0);
                mma16816f(oacc[2 * np + 1], ph[ks], b1);
            }
        }
        __syncthreads();    // stage fully consumed before reload overwrites it

        if (c + 2 < FL_NIT)
            fl_load(sb + 16384 + (uint32_t)(c & 1) * 32768, b, (c + 2) * 64, t);
    }

    // quad-reduce row sums once
    lsum0 += __shfl_xor_sync(~0u, lsum0, 1);
    lsum0 += __shfl_xor_sync(~0u, lsum0, 2);
    lsum1 += __shfl_xor_sync(~0u, lsum1, 1);
    lsum1 += __shfl_xor_sync(~0u, lsum1, 2);
    const float inv0 = 1.0f / lsum0;
    const float inv1 = 1.0f / lsum1;

    // ---------------- epilogue: O /= l, write, fused BN partials -------------
    __syncthreads();
    float* sf = (float*)dsm;                 // [64][132] staging
    const int rowl = lane >> 2, coll = (lane & 3) * 2;
    #pragma unroll
    for (int nf = 0; nf < 16; ++nf) {
        float* p0 = sf + (size_t)(R + rowl) * 132 + nf * 8 + coll;
        float* p1 = sf + (size_t)(R + 8 + rowl) * 132 + nf * 8 + coll;
        p0[0] = oacc[nf][0] * inv0;
        p0[1] = oacc[nf][1] * inv0;
        p1[0] = oacc[nf][2] * inv1;
        p1[1] = oacc[nf][3] * inv1;
    }
    __syncthreads();

    float* dst = g_o + ((size_t)(b * NN + i0)) * HH;
    float s4a[4] = {0.f, 0.f, 0.f, 0.f}, q4[4] = {0.f, 0.f, 0.f, 0.f};
    #pragma unroll
    for (int e = t; e < 2048; e += 128) {    // 64 rows x 32 float4-cols
        int r = e >> 5, c4 = (e & 31) * 4;
        float4 v = *(float4*)(sf + (size_t)r * 132 + c4);
        *(float4*)(dst + (size_t)r * HH + c4) = v;
        s4a[0] += v.x; q4[0] += v.x * v.x;
        s4a[1] += v.y; q4[1] += v.y * v.y;
        s4a[2] += v.z; q4[2] += v.z * v.z;
        s4a[3] += v.w; q4[3] += v.w * v.w;
    }
    float* red  = (float*)(dsm + 36864);     // [128 ch][4 grp] sums
    float* red2 = (float*)(dsm + 38912);     // [128 ch][4 grp] sumsq
    const int cbase = (t & 31) * 4, grp = t >> 5;
    #pragma unroll
    for (int i = 0; i < 4; ++i) {
        red[(cbase + i) * 4 + grp]  = s4a[i];
        red2[(cbase + i) * 4 + grp] = q4[i];
    }
    __syncthreads();
    if (t < 128) {
        float ss = 0.0f, qq = 0.0f;
        #pragma unroll
        for (int g2 = 0; g2 < 4; ++g2) {
            ss += red[t * 4 + g2];
            qq += red2[t * 4 + g2];
        }
        atomicAdd(&g_psum[t], ss);
        atomicAdd(&g_psq[t], qq);
    }
}

// ---------------------------------------------------------------------------
// Kernel 3: fused BN epilogue (stats finalize inlined; smem tile transpose)
// ---------------------------------------------------------------------------
__global__ __launch_bounds__(256, 1)
void final_kernel(const float* __restrict__ x,
                  const float* __restrict__ bnw,
                  const float* __restrict__ bnb,
                  const float* __restrict__ gamma,
                  float* __restrict__ out)
{
    __shared__ float sO[32 * 132];
    const int b = blockIdx.y, n0 = blockIdx.x * 32;
    const int t = threadIdx.x;

    #pragma unroll
    for (int e = t; e < 1024; e += 256) {
        int r = e >> 5, c4 = (e & 31) * 4;
        *(float4*)&sO[r * 132 + c4] =
            *(const float4*)&g_o[((size_t)(b * NN + n0 + r)) * HH + c4];
    }
    __syncthreads();
    const float g = __ldg(gamma);
    const float invn = 1.0f / 16384.0f;
    #pragma unroll
    for (int e = t; e < 1024; e += 256) {
        int c = e >> 3, n4 = (e & 7) * 4;
        float mean = g_psum[c] * invn;
        float var = g_psq[c] * invn - mean * mean;
        float rstd = rsqrtf(var + EPSV);
        float wc = __ldg(&bnw[c]), bc = __ldg(&bnb[c]);
        size_t gi = ((size_t)(b * CC + c)) * NN + n0 + n4;
        float4 xv = *(const float4*)&x[gi];
        float4 r;
        r.x = g * ((sO[(n4 + 0) * 132 + c] - mean) * rstd * wc + bc) + xv.x;
        r.y = g * ((sO[(n4 + 1) * 132 + c] - mean) * rstd * wc + bc) + xv.y;
        r.z = g * ((sO[(n4 + 2) * 132 + c] - mean) * rstd * wc + bc) + xv.z;
        r.w = g * ((sO[(n4 + 3) * 132 + c] - mean) * rstd * wc + bc) + xv.w;
        *(float4*)&out[gi] = r;
    }
}

// ---------------------------------------------------------------------------
extern "C" void kernel_launch(void* const* d_in, const int* in_sizes, int n_in,
                              void* d_out, int out_size)
{
    (void)in_sizes; (void)n_in; (void)out_size;
    const float* x     = (const float*)d_in[0];
    const float* Wq    = (const float*)d_in[1];
    const float* bq    = (const float*)d_in[2];
    const float* Wk    = (const float*)d_in[3];
    const float* bk    = (const float*)d_in[4];
    const float* Wv    = (const float*)d_in[5];
    const float* bv    = (const float*)d_in[6];
    const float* bnw   = (const float*)d_in[7];
    const float* bnb   = (const float*)d_in[8];
    const float* gamma = (const float*)d_in[9];
    float* out = (float*)d_out;

    cudaFuncSetAttribute(qkv2_kernel,  cudaFuncAttributeMaxDynamicSharedMemorySize, QKV2_SMEM);
    cudaFuncSetAttribute(flash_kernel, cudaFuncAttributeMaxDynamicSharedMemorySize, FL_SMEM);

    qkv2_kernel<<<dim3(NN / 128, BB, 3), 256, QKV2_SMEM>>>(x, Wq, Wk, Wv, bq, bk, bv);
    flash_kernel<<<dim3(NN / 64, BB), 128, FL_SMEM>>>();
    final_kernel<<<dim3(NN / 32, BB), 256>>>(x, bnw, bnb, gamma, out);
}